// round 14
// baseline (speedup 1.0000x reference)
#include <cuda_runtime.h>
#include <cuda_fp16.h>
#include <cstdint>

// ---------------------------------------------------------------------------
// HybridModel, Round 13:
//   prep: one-time fp16 weight repack (conv1 + conv2 + conv3)
//   conv1: fp16 mma m16n8k16, C8 records (16B pixel stride: conflict-free)
//   conv2/conv3: fp16 mma + ldmatrix, int4 weight staging (R11, proven)
//   head fused into conv3 kernel (analytic quantum features)
// ---------------------------------------------------------------------------

typedef uint32_t u32;

__device__ __forceinline__ void mma16(float* d, u32 a0, u32 a1, u32 a2, u32 a3,
                                      u32 b0, u32 b1) {
    asm("mma.sync.aligned.m16n8k16.row.col.f32.f16.f16.f32 "
        "{%0,%1,%2,%3},{%4,%5,%6,%7},{%8,%9},{%0,%1,%2,%3};"
        : "+f"(d[0]), "+f"(d[1]), "+f"(d[2]), "+f"(d[3])
        : "r"(a0), "r"(a1), "r"(a2), "r"(a3), "r"(b0), "r"(b1));
}

__device__ __forceinline__ void ldsm_x4(u32& r0, u32& r1, u32& r2, u32& r3,
                                        u32 addr) {
    asm volatile("ldmatrix.sync.aligned.m8n8.x4.shared.b16 {%0,%1,%2,%3}, [%4];"
        : "=r"(r0), "=r"(r1), "=r"(r2), "=r"(r3) : "r"(addr));
}

__device__ __forceinline__ u32 s2u(const void* p) {
    return (u32)__cvta_generic_to_shared(p);
}

__device__ __forceinline__ u32 pack_h2(float lo, float hi) {
    __half2 h = __floats2half2_rn(lo, hi);
    return *(u32*)&h;
}

// fp16 NHWC intermediates
__device__ __half g_h1h[512 * 32 * 32 * 16];   // 16.8 MB, [b][y][x][c16]
__device__ __half g_h2h[512 * 16 * 16 * 32];   //  8.4 MB, [b][y][x][c32]
// prepacked fp16 weights (exact smem layouts, tails zeroed)
__device__ __align__(16) __half g_wb1h[16 * 56];
__device__ __align__(16) __half g_wb2h[32 * 152];
__device__ __align__(16) __half g_wb3h[64 * 296];

// ---------------------------------------------------------------------------
// prep: repack all conv weights to fp16 padded layouts (one launch).
// ---------------------------------------------------------------------------
__global__ __launch_bounds__(256) void prep_kernel(
    const float* __restrict__ w1, const float* __restrict__ w2,
    const float* __restrict__ w3)
{
    int i = blockIdx.x * 256 + threadIdx.x;
    if (i < 16 * 56) {
        int oc = i / 56, k = i % 56;
        int tap = k >> 2, ic = k & 3;
        float v = (k < 48 && ic < 3 && tap < 9) ? w1[oc * 27 + ic * 9 + tap] : 0.f;
        g_wb1h[i] = __float2half_rn(v);
    }
    if (i < 32 * 152) {
        int oc = i / 152, k = i % 152;
        float v = 0.f;
        if (k < 144) { int tap = k >> 4, ic = k & 15; v = w2[oc * 144 + ic * 9 + tap]; }
        g_wb2h[i] = __float2half_rn(v);
    }
    if (i < 64 * 296) {
        int oc = i / 296, k = i % 296;
        float v = 0.f;
        if (k < 288) { int tap = k >> 5, ic = k & 31; v = w3[(oc * 32 + ic) * 9 + tap]; }
        g_wb3h[i] = __float2half_rn(v);
    }
}

// ---------------------------------------------------------------------------
// conv1: (b,3,64,64) f32 -> bn/relu/pool -> (b,32,32,16) half NHWC
// grid (2,2,512) x 512 thr. Quarter image: pre-pool 32x32 -> M=1024
// (64 mtiles, 4/warp), N=16 (2 ntiles), K=48 (3 ktiles; k = tap*4+ic).
// sina = 34x34 halo of 8-half records (C4 padded to 16B: conflict-free).
// ---------------------------------------------------------------------------
__global__ __launch_bounds__(512, 2) void conv1_kernel(
    const float* __restrict__ x,
    const float* __restrict__ cb, const float* __restrict__ bg,
    const float* __restrict__ bb, const float* __restrict__ bm,
    const float* __restrict__ bv)
{
    __shared__ __align__(16) __half sina[1156 * 8];   // 18496 B (spool overlays)
    __shared__ __align__(16) __half wbc[16 * 56];     //  1792 B
    __shared__ __align__(16) float buf[512 * 8];      // 16384 B
    __shared__ float ssc[16], ssh[16];
    __half* spool = sina;                             // overlay: 256*24 halves

    int b = blockIdx.z, ty = blockIdx.y, tx = blockIdx.x;
    int tid = threadIdx.x;

    // weights from prepacked global (112 int4)
    if (tid < 112) ((int4*)wbc)[tid] = ((const int4*)g_wb1h)[tid];
    if (tid < 16) {
        float inv = bg[tid] * rsqrtf(bv[tid] + 1e-5f);
        ssc[tid] = inv;
        ssh[tid] = (cb[tid] - bm[tid]) * inv + bb[tid];
    }
    // stage input halo as C8 records (3 channels + zeros)
    int y0 = ty * 32 - 1, x0 = tx * 32 - 1;
    const float* xb = x + b * 3 * 64 * 64;
    for (int i = tid; i < 1156; i += 512) {
        int yy = i / 34, xx = i % 34;
        int gy = y0 + yy, gx = x0 + xx;
        float v0 = 0.f, v1 = 0.f, v2 = 0.f;
        if ((unsigned)gy < 64u && (unsigned)gx < 64u) {
            int o = gy * 64 + gx;
            v0 = xb[o];
            v1 = xb[4096 + o];
            v2 = xb[8192 + o];
        }
        *(int4*)(sina + i * 8) =
            make_int4(pack_h2(v0, v1), pack_h2(v2, 0.f), 0, 0);
    }
    __syncthreads();

    int lane = tid & 31, warp = tid >> 5;
    int g = lane >> 2, tg = lane & 3;

    // A tap offsets (halves) for kt 0..1, j 0..1: tap = kt*4 + j*2 + (tg>>1)
    int aoffH[2][2];
#pragma unroll
    for (int kt = 0; kt < 2; kt++)
#pragma unroll
        for (int j = 0; j < 2; j++) {
            int t = kt * 4 + j * 2 + (tg >> 1);
            aoffH[kt][j] = ((t / 3) * 34 + (t % 3)) * 8 + 2 * (tg & 1);
        }
    // kt=2: only tap 8 (tg<2) on j=0; j=1 all zero
    int aoff8 = (2 * 34 + 2) * 8 + 2 * (tg & 1);
    bool tap8 = (tg < 2);

    float acc[4][2][4];
#pragma unroll
    for (int i = 0; i < 4; i++)
#pragma unroll
        for (int nt = 0; nt < 2; nt++)
#pragma unroll
            for (int r = 0; r < 4; r++) acc[i][nt][r] = 0.f;

    // per-mtile record bases (halves)
    int rrb[4];
#pragma unroll
    for (int i = 0; i < 4; i++) {
        int m0 = (warp + 16 * i) * 16 + g;
        rrb[i] = ((m0 >> 5) * 34 + (m0 & 31)) * 8;
    }

#pragma unroll
    for (int kt = 0; kt < 2; kt++) {
        const __half* wrow = wbc + g * 56 + kt * 16 + 2 * tg;
        u32 b0a = *(const u32*)wrow;
        u32 b1a = *(const u32*)(wrow + 8);
        u32 b0b = *(const u32*)(wrow + 8 * 56);
        u32 b1b = *(const u32*)(wrow + 8 * 56 + 8);
        int o0 = aoffH[kt][0], o1 = aoffH[kt][1];
#pragma unroll
        for (int i = 0; i < 4; i++) {
            const __half* base = sina + rrb[i];
            u32 a0 = *(const u32*)(base + o0);
            u32 a1 = *(const u32*)(base + 64 + o0);   // +8 records
            u32 a2 = *(const u32*)(base + o1);
            u32 a3 = *(const u32*)(base + 64 + o1);
            mma16(acc[i][0], a0, a1, a2, a3, b0a, b1a);
            mma16(acc[i][1], a0, a1, a2, a3, b0b, b1b);
        }
    }
    {   // kt = 2: tap 8 only
        const __half* wrow = wbc + g * 56 + 32 + 2 * tg;
        u32 b0a = *(const u32*)wrow;
        u32 b1a = *(const u32*)(wrow + 8);
        u32 b0b = *(const u32*)(wrow + 8 * 56);
        u32 b1b = *(const u32*)(wrow + 8 * 56 + 8);
#pragma unroll
        for (int i = 0; i < 4; i++) {
            const __half* base = sina + rrb[i];
            u32 a0 = 0, a1 = 0;
            if (tap8) {
                a0 = *(const u32*)(base + aoff8);
                a1 = *(const u32*)(base + 64 + aoff8);
            }
            mma16(acc[i][0], a0, a1, 0u, 0u, b0a, b1a);
            mma16(acc[i][1], a0, a1, 0u, 0u, b0b, b1b);
        }
    }

    // epilogue: bounce via buf (f32), pool, pack into spool (overlay on sina)
#pragma unroll 1
    for (int nt = 0; nt < 2; nt++) {
#pragma unroll 1
        for (int h = 0; h < 2; h++) {
            __syncthreads();
#pragma unroll
            for (int ii = 0; ii < 2; ii++) {
                int i = 2 * h + ii;
                int m0 = (warp + 16 * i) * 16 + g;
                int ml = m0 - h * 512;
                buf[ml * 8 + tg * 2]       = acc[i][nt][0];
                buf[ml * 8 + tg * 2 + 1]   = acc[i][nt][1];
                buf[(ml + 8) * 8 + tg * 2]     = acc[i][nt][2];
                buf[(ml + 8) * 8 + tg * 2 + 1] = acc[i][nt][3];
            }
            __syncthreads();
            for (int ii = tid; ii < 1024; ii += 512) {
                int oc = ii >> 7, pp = ii & 127;
                int r = pp >> 4, Px = pp & 15;
                int ml = (2 * r) * 32 + 2 * Px;
                int c = nt * 8 + oc;
                float sc = ssc[c], sh = ssh[c];
                float v0 = fmaxf(buf[ml * 8 + oc] * sc + sh, 0.f);
                float v1 = fmaxf(buf[(ml + 1) * 8 + oc] * sc + sh, 0.f);
                float v2 = fmaxf(buf[(ml + 32) * 8 + oc] * sc + sh, 0.f);
                float v3 = fmaxf(buf[(ml + 33) * 8 + oc] * sc + sh, 0.f);
                int Py = h * 8 + r;
                spool[(Py * 16 + Px) * 24 + c] =
                    __float2half_rn(fmaxf(fmaxf(v0, v1), fmaxf(v2, v3)));
            }
        }
    }
    __syncthreads();

    {   // cooperative 16B stores: 256 pixels x 2 chunks
        int pix = tid >> 1, j = tid & 1;
        int Py = pix >> 4, Px = pix & 15;
        int gy = ty * 16 + Py, gx = tx * 16 + Px;
        *(int4*)(g_h1h + (((size_t)b * 32 + gy) * 32 + gx) * 16 + j * 8) =
            *(const int4*)(spool + pix * 24 + j * 8);
    }
}

// ---------------------------------------------------------------------------
// conv2: (b,32,32,16) half NHWC -> (b,16,16,32) half NHWC. (R11, proven)
// ---------------------------------------------------------------------------
__global__ __launch_bounds__(512) void conv2_kernel(
    const float* __restrict__ cb,
    const float* __restrict__ bg, const float* __restrict__ bb,
    const float* __restrict__ bm, const float* __restrict__ bv)
{
    __shared__ __align__(16) char usmem[36864];
    __shared__ float ssc[32], ssh[32];
    __half* sp2 = (__half*)usmem;
    __half* wb2 = (__half*)(usmem + 15552);
    float*  buf = (float*)usmem;

    int b = blockIdx.z, ty = blockIdx.y, tx = blockIdx.x;
    int tid = threadIdx.x;

    for (int i = tid; i < 608; i += 512)
        ((int4*)wb2)[i] = ((const int4*)g_wb2h)[i];
    if (tid < 32) {
        float inv = bg[tid] * rsqrtf(bv[tid] + 1e-5f);
        ssc[tid] = inv;
        ssh[tid] = (cb[tid] - bm[tid]) * inv + bb[tid];
    }
    int y0 = ty * 16 - 1, x0 = tx * 16 - 1;
    const __half* ib = g_h1h + (size_t)b * 1024 * 16;
    for (int i = tid; i < 324 * 2; i += 512) {
        int pix = i >> 1, j = i & 1;
        int yy = pix / 18, xx = pix % 18;
        int gy = y0 + yy, gx = x0 + xx;
        int4 v = make_int4(0, 0, 0, 0);
        if ((unsigned)gy < 32u && (unsigned)gx < 32u)
            v = *(const int4*)(ib + ((size_t)gy * 32 + gx) * 16 + j * 8);
        *(int4*)(sp2 + pix * 24 + j * 8) = v;
    }
    __syncthreads();

    int lane = tid & 31, warp = tid >> 5;
    int g = lane >> 2, tg = lane & 3;
    int mt = warp;

    int pxl = lane & 15, kha = lane >> 4;
    u32 aB = s2u(sp2) + (u32)(mt * 18 + pxl) * 48 + kha * 16;
    int ocl = (lane & 7) | ((lane >> 4) << 3);
    int khb = (lane >> 3) & 1;
    u32 bB0 = s2u(wb2) + (u32)ocl * 304 + khb * 16;
    u32 bB1 = bB0 + 16 * 304;

    float acc[4][4];
#pragma unroll
    for (int nt = 0; nt < 4; nt++)
#pragma unroll
        for (int r = 0; r < 4; r++) acc[nt][r] = 0.f;

#pragma unroll
    for (int tap = 0; tap < 9; tap++) {
        const int ky = tap / 3, kx = tap % 3;
        u32 a0, a1, a2, a3;
        ldsm_x4(a0, a1, a2, a3, aB + (u32)(ky * 18 + kx) * 48);
        u32 p00, p01, p10, p11, p20, p21, p30, p31;
        ldsm_x4(p00, p01, p10, p11, bB0 + tap * 32);
        ldsm_x4(p20, p21, p30, p31, bB1 + tap * 32);
        mma16(acc[0], a0, a1, a2, a3, p00, p01);
        mma16(acc[1], a0, a1, a2, a3, p10, p11);
        mma16(acc[2], a0, a1, a2, a3, p20, p21);
        mma16(acc[3], a0, a1, a2, a3, p30, p31);
    }

    __syncthreads();

    int m0 = mt * 16 + g;
#pragma unroll
    for (int nt = 0; nt < 4; nt++) {
        buf[m0 * 36 + nt * 8 + 2 * tg]           = acc[nt][0];
        buf[m0 * 36 + nt * 8 + 2 * tg + 1]       = acc[nt][1];
        buf[(m0 + 8) * 36 + nt * 8 + 2 * tg]     = acc[nt][2];
        buf[(m0 + 8) * 36 + nt * 8 + 2 * tg + 1] = acc[nt][3];
    }
    __syncthreads();

    {
        int pix = tid >> 3, ocg = tid & 7;
        int r = pix >> 3, Px = pix & 7;
        int ml = (2 * r) * 16 + 2 * Px;
        int oc0 = ocg * 4;
        float pv[4];
#pragma unroll
        for (int cc = 0; cc < 4; cc++) {
            int c = oc0 + cc;
            float sc = ssc[c], sh = ssh[c];
            float v0 = fmaxf(buf[ml * 36 + c] * sc + sh, 0.f);
            float v1 = fmaxf(buf[(ml + 1) * 36 + c] * sc + sh, 0.f);
            float v2 = fmaxf(buf[(ml + 16) * 36 + c] * sc + sh, 0.f);
            float v3 = fmaxf(buf[(ml + 17) * 36 + c] * sc + sh, 0.f);
            pv[cc] = fmaxf(fmaxf(v0, v1), fmaxf(v2, v3));
        }
        int gy = ty * 8 + r, gx = tx * 8 + Px;
        int2 ov = make_int2(pack_h2(pv[0], pv[1]), pack_h2(pv[2], pv[3]));
        *(int2*)(g_h2h + (((size_t)b * 16 + gy) * 16 + gx) * 32 + oc0) = ov;
    }
}

// ---------------------------------------------------------------------------
// conv3 + head fused, 2 blocks/SM. (R11, proven)
// ---------------------------------------------------------------------------
#define C3_SFE   69632
#define C3_BN    86016
#define C3_TOTAL 86528
#define H_SPART 0
#define H_SCOS  16384
#define H_SFT   16896
#define H_SCP   19200

__global__ __launch_bounds__(512, 2) void conv3_head_kernel(
    const float* __restrict__ cb,
    const float* __restrict__ bg, const float* __restrict__ bb,
    const float* __restrict__ bm, const float* __restrict__ bv,
    const float* __restrict__ pw, const float* __restrict__ pb,
    const float* __restrict__ cw, const float* __restrict__ cbias,
    float* __restrict__ out)
{
    extern __shared__ char smem_raw[];
    __half* sp3 = (__half*)(smem_raw + 0);
    __half* wb3 = (__half*)(smem_raw + 25920);
    float*  buf = (float*)(smem_raw + 0);
    float*  sfeats = (float*)(smem_raw + C3_SFE);
    float*  ssc = (float*)(smem_raw + C3_BN);
    float*  ssh = ssc + 64;

    int b = blockIdx.x, tid = threadIdx.x;

    for (int i = tid; i < 2368; i += 512)
        ((int4*)wb3)[i] = ((const int4*)g_wb3h)[i];
    if (tid < 64) {
        float inv = bg[tid] * rsqrtf(bv[tid] + 1e-5f);
        ssc[tid] = inv;
        ssh[tid] = (cb[tid] - bm[tid]) * inv + bb[tid];
    }
    const __half* ib = g_h2h + (size_t)b * 256 * 32;
    for (int i = tid; i < 324 * 4; i += 512) {
        int pix = i >> 2, j = i & 3;
        int yy = pix / 18, xx = pix % 18;
        int gy = yy - 1, gx = xx - 1;
        int4 v = make_int4(0, 0, 0, 0);
        if ((unsigned)gy < 16u && (unsigned)gx < 16u)
            v = *(const int4*)(ib + ((size_t)gy * 16 + gx) * 32 + j * 8);
        *(int4*)(sp3 + pix * 40 + j * 8) = v;
    }
    __syncthreads();

    int lane = tid & 31, warp = tid >> 5;
    int g = lane >> 2, tg = lane & 3;
    int mt = warp;

    int pxl = lane & 15, kha = lane >> 4;
    u32 aB = s2u(sp3) + (u32)(mt * 18 + pxl) * 80 + kha * 16;
    int ocl = (lane & 7) | ((lane >> 4) << 3);
    int khb = (lane >> 3) & 1;
    u32 bB = s2u(wb3) + (u32)ocl * 592 + khb * 16;

    float acc[8][4];
#pragma unroll
    for (int nt = 0; nt < 8; nt++)
#pragma unroll
        for (int r = 0; r < 4; r++) acc[nt][r] = 0.f;

#pragma unroll
    for (int kt = 0; kt < 18; kt++) {
        const int tap = kt >> 1, h = kt & 1;
        const int ky = tap / 3, kx = tap % 3;
        u32 a0, a1, a2, a3;
        ldsm_x4(a0, a1, a2, a3, aB + (u32)(ky * 18 + kx) * 80 + h * 32);
#pragma unroll
        for (int p = 0; p < 4; p++) {
            u32 q0, q1, q2, q3;
            ldsm_x4(q0, q1, q2, q3, bB + (u32)p * 16 * 592 + kt * 32);
            mma16(acc[2 * p],     a0, a1, a2, a3, q0, q1);
            mma16(acc[2 * p + 1], a0, a1, a2, a3, q2, q3);
        }
    }

    __syncthreads();

    int m0 = mt * 16 + g;
#pragma unroll
    for (int nt = 0; nt < 8; nt++) {
        buf[m0 * 68 + nt * 8 + 2 * tg]           = acc[nt][0];
        buf[m0 * 68 + nt * 8 + 2 * tg + 1]       = acc[nt][1];
        buf[(m0 + 8) * 68 + nt * 8 + 2 * tg]     = acc[nt][2];
        buf[(m0 + 8) * 68 + nt * 8 + 2 * tg + 1] = acc[nt][3];
    }
    __syncthreads();

    {
        int pix = tid >> 3, ocg = tid & 7;
        int r = pix >> 3, Px = pix & 7;
        int ml = (2 * r) * 16 + 2 * Px;
        int oc0 = ocg * 8;
#pragma unroll
        for (int cc = 0; cc < 8; cc++) {
            int c = oc0 + cc;
            float sc = ssc[c], sh = ssh[c];
            float v0 = fmaxf(buf[ml * 68 + c] * sc + sh, 0.f);
            float v1 = fmaxf(buf[(ml + 1) * 68 + c] * sc + sh, 0.f);
            float v2 = fmaxf(buf[(ml + 16) * 68 + c] * sc + sh, 0.f);
            float v3 = fmaxf(buf[(ml + 17) * 68 + c] * sc + sh, 0.f);
            sfeats[c * 64 + r * 8 + Px] = fmaxf(fmaxf(v0, v1), fmaxf(v2, v3));
        }
    }
    __syncthreads();

    // ---- head ----
    float* spart = (float*)(smem_raw + H_SPART);
    float* scos  = (float*)(smem_raw + H_SCOS);
    float* sfeat = (float*)(smem_raw + H_SFT);
    float* scp   = (float*)(smem_raw + H_SCP);

    {
        int k = tid >> 5, cs = tid & 31;
        float part[8];
#pragma unroll
        for (int d = 0; d < 8; d++) part[d] = 0.f;
        const float* fr = sfeats + k * 256 + cs * 8;
        const float* wr = pw + k * 2048 + cs * 64;
#pragma unroll
        for (int c = 0; c < 8; c++) {
            float fv = fr[c];
            float4 w0 = ((const float4*)(wr + c * 8))[0];
            float4 w1 = ((const float4*)(wr + c * 8))[1];
            part[0] += fv * w0.x; part[1] += fv * w0.y;
            part[2] += fv * w0.z; part[3] += fv * w0.w;
            part[4] += fv * w1.x; part[5] += fv * w1.y;
            part[6] += fv * w1.z; part[7] += fv * w1.w;
        }
        __syncthreads();
#pragma unroll
        for (int d = 0; d < 8; d++) spart[tid * 8 + d] = part[d];
    }
    __syncthreads();

    if (tid < 128) {
        int k = tid >> 3, d = tid & 7;
        float z = pb[k * 8 + d];
#pragma unroll
        for (int cs = 0; cs < 32; cs++) z += spart[(k * 32 + cs) * 8 + d];
        scos[tid] = cosf(0.5f * tanhf(z));
    }
    __syncthreads();

    if (tid < 16) {
        const float* c8 = scos + tid * 8;
        float* fo = sfeat + tid * 36;
        float p = 1.f;
#pragma unroll
        for (int q = 0; q < 8; q++) { p *= c8[q]; fo[q] = p; }
        int idx = 8;
#pragma unroll
        for (int i = 0; i < 8; i++) {
#pragma unroll
            for (int j = i + 1; j < 8; j++) {
                float p2 = 1.f;
                for (int m = i + 1; m <= j; m++) p2 *= c8[m];
                fo[idx++] = p2;
            }
        }
    }
    __syncthreads();

    if (tid < 80) {
        int cls = tid >> 3, ch = tid & 7;
        const float* wrow = cw + cls * 576 + ch * 72;
        const float* fr2 = sfeat + ch * 72;
        float s = 0.f;
#pragma unroll 8
        for (int j = 0; j < 72; j++) s += fr2[j] * wrow[j];
        scp[cls * 8 + ch] = s;
    }
    __syncthreads();

    if (tid < 10) {
        float o = cbias[tid];
#pragma unroll
        for (int ch = 0; ch < 8; ch++) o += scp[tid * 8 + ch];
        out[b * 10 + tid] = o;
    }
}

// ---------------------------------------------------------------------------
extern "C" void kernel_launch(void* const* d_in, const int* in_sizes, int n_in,
                              void* d_out, int out_size)
{
    const float* x    = (const float*)d_in[0];
    const float* c1w  = (const float*)d_in[1];
    const float* c1b  = (const float*)d_in[2];
    const float* g1   = (const float*)d_in[3];
    const float* b1   = (const float*)d_in[4];
    const float* m1   = (const float*)d_in[5];
    const float* v1   = (const float*)d_in[6];
    const float* c2w  = (const float*)d_in[7];
    const float* c2b  = (const float*)d_in[8];
    const float* g2   = (const float*)d_in[9];
    const float* b2   = (const float*)d_in[10];
    const float* m2   = (const float*)d_in[11];
    const float* v2   = (const float*)d_in[12];
    const float* c3w  = (const float*)d_in[13];
    const float* c3b  = (const float*)d_in[14];
    const float* g3   = (const float*)d_in[15];
    const float* b3   = (const float*)d_in[16];
    const float* m3   = (const float*)d_in[17];
    const float* v3   = (const float*)d_in[18];
    const float* pw   = (const float*)d_in[19];
    const float* pb   = (const float*)d_in[20];
    const float* cw   = (const float*)d_in[21];
    const float* cbias= (const float*)d_in[22];
    float* out = (float*)d_out;

    cudaFuncSetAttribute(conv3_head_kernel,
                         cudaFuncAttributeMaxDynamicSharedMemorySize, C3_TOTAL);

    prep_kernel<<<74, 256>>>(c1w, c2w, c3w);
    conv1_kernel<<<dim3(2, 2, 512), 512>>>(x, c1b, g1, b1, m1, v1);
    conv2_kernel<<<dim3(2, 2, 512), 512>>>(c2b, g2, b2, m2, v2);
    conv3_head_kernel<<<512, 512, C3_TOTAL>>>(c3b, g3, b3, m3, v3,
                                              pw, pb, cw, cbias, out);
}

// round 15
// speedup vs baseline: 1.4467x; 1.4467x over previous
#include <cuda_runtime.h>
#include <cuda_fp16.h>
#include <cstdint>

// ---------------------------------------------------------------------------
// HybridModel, Round 14:
//   prep: one-time fp16 weight repack for conv2/conv3
//   conv1: FFMA2 direct conv, 512 thr (R10/R12, proven 64.7us)
//   conv2: fp16 mma + ldmatrix, int4 weight staging (R11, proven)
//   conv3_head: warp tiling 2 mtiles x 4 ntiles (balanced LDSM, 2x ILP)
// ---------------------------------------------------------------------------

typedef uint32_t u32;
typedef unsigned long long ull;

__device__ __forceinline__ void ffma2(ull& d, ull a, ull b) {
    asm("fma.rn.f32x2 %0, %1, %2, %0;" : "+l"(d) : "l"(a), "l"(b));
}
__device__ __forceinline__ ull dup2(float v) {
    ull r;
    asm("mov.b64 %0, {%1, %1};" : "=l"(r) : "f"(v));
    return r;
}
__device__ __forceinline__ void unpack2(ull v, float& lo, float& hi) {
    asm("mov.b64 {%0, %1}, %2;" : "=f"(lo), "=f"(hi) : "l"(v));
}

__device__ __forceinline__ void mma16(float* d, u32 a0, u32 a1, u32 a2, u32 a3,
                                      u32 b0, u32 b1) {
    asm("mma.sync.aligned.m16n8k16.row.col.f32.f16.f16.f32 "
        "{%0,%1,%2,%3},{%4,%5,%6,%7},{%8,%9},{%0,%1,%2,%3};"
        : "+f"(d[0]), "+f"(d[1]), "+f"(d[2]), "+f"(d[3])
        : "r"(a0), "r"(a1), "r"(a2), "r"(a3), "r"(b0), "r"(b1));
}

__device__ __forceinline__ void ldsm_x4(u32& r0, u32& r1, u32& r2, u32& r3,
                                        u32 addr) {
    asm volatile("ldmatrix.sync.aligned.m8n8.x4.shared.b16 {%0,%1,%2,%3}, [%4];"
        : "=r"(r0), "=r"(r1), "=r"(r2), "=r"(r3) : "r"(addr));
}

__device__ __forceinline__ u32 s2u(const void* p) {
    return (u32)__cvta_generic_to_shared(p);
}

__device__ __forceinline__ u32 pack_h2(float lo, float hi) {
    __half2 h = __floats2half2_rn(lo, hi);
    return *(u32*)&h;
}

// fp16 NHWC intermediates
__device__ __half g_h1h[512 * 32 * 32 * 16];   // 16.8 MB, [b][y][x][c16]
__device__ __half g_h2h[512 * 16 * 16 * 32];   //  8.4 MB, [b][y][x][c32]
// prepacked fp16 weights (exact smem layouts, tails zeroed)
__device__ __align__(16) __half g_wb2h[32 * 152];
__device__ __align__(16) __half g_wb3h[64 * 296];

// ---------------------------------------------------------------------------
// prep: repack conv2/conv3 weights to fp16 padded layouts (one launch).
// ---------------------------------------------------------------------------
__global__ __launch_bounds__(256) void prep_kernel(
    const float* __restrict__ w2, const float* __restrict__ w3)
{
    int i = blockIdx.x * 256 + threadIdx.x;
    if (i < 32 * 152) {
        int oc = i / 152, k = i % 152;
        float v = 0.f;
        if (k < 144) { int tap = k >> 4, ic = k & 15; v = w2[oc * 144 + ic * 9 + tap]; }
        g_wb2h[i] = __float2half_rn(v);
    }
    if (i < 64 * 296) {
        int oc = i / 296, k = i % 296;
        float v = 0.f;
        if (k < 288) { int tap = k >> 5, ic = k & 31; v = w3[(oc * 32 + ic) * 9 + tap]; }
        g_wb3h[i] = __float2half_rn(v);
    }
}

// ---------------------------------------------------------------------------
// conv1: (b,3,64,64) f32 -> bn/relu/pool -> (b,32,32,16) half NHWC (R12)
// ---------------------------------------------------------------------------
__global__ __launch_bounds__(512, 2) void conv1_kernel(
    const float* __restrict__ x, const float* __restrict__ w,
    const float* __restrict__ cb, const float* __restrict__ bg,
    const float* __restrict__ bb, const float* __restrict__ bm,
    const float* __restrict__ bv)
{
    __shared__ __align__(16) float sp[3][34][34];
    __shared__ __align__(16) float swt[3][9][16];
    __shared__ float ssc[16], ssh[16];

    int b = blockIdx.z, ty = blockIdx.y, tx = blockIdx.x;
    int tid = threadIdx.x;

    for (int i = tid; i < 16 * 27; i += 512) {
        int oc = i / 27, r = i % 27, ic = r / 9, k = r % 9;
        swt[ic][k][oc] = w[i];
    }
    if (tid < 16) {
        float inv = bg[tid] * rsqrtf(bv[tid] + 1e-5f);
        ssc[tid] = inv;
        ssh[tid] = (cb[tid] - bm[tid]) * inv + bb[tid];
    }
    int y0 = ty * 32 - 1, x0 = tx * 32 - 1;
    const float* xb = x + b * 3 * 64 * 64;
    for (int i = tid; i < 3 * 34 * 34; i += 512) {
        int ic = i / 1156, r = i % 1156, yy = r / 34, xx = r % 34;
        int gy = y0 + yy, gx = x0 + xx;
        float val = 0.f;
        if ((unsigned)gy < 64u && (unsigned)gx < 64u)
            val = xb[(ic * 64 + gy) * 64 + gx];
        sp[ic][yy][xx] = val;
    }
    __syncthreads();

    int pix = tid & 255, h = tid >> 8;
    int py = pix >> 4, px = pix & 15;
    int by = 2 * py, bx = 2 * px;

    ull acc[4][4];
#pragma unroll
    for (int p = 0; p < 4; p++)
#pragma unroll
        for (int o = 0; o < 4; o++) acc[p][o] = 0ull;

#pragma unroll 1
    for (int ic = 0; ic < 3; ic++) {
#pragma unroll
        for (int k = 0; k < 9; k++) {
            const int ky = k / 3, kx = k % 3;
            ull d00 = dup2(sp[ic][by + ky][bx + kx]);
            ull d01 = dup2(sp[ic][by + ky][bx + kx + 1]);
            ull d10 = dup2(sp[ic][by + ky + 1][bx + kx]);
            ull d11 = dup2(sp[ic][by + ky + 1][bx + kx + 1]);
            const ull* wp = (const ull*)swt[ic][k] + h * 4;
#pragma unroll
            for (int o = 0; o < 4; o++) {
                ull wv = wp[o];
                ffma2(acc[0][o], d00, wv);
                ffma2(acc[1][o], d01, wv);
                ffma2(acc[2][o], d10, wv);
                ffma2(acc[3][o], d11, wv);
            }
        }
    }

    u32 r4[4];
#pragma unroll
    for (int o = 0; o < 4; o++) {
        float a0l, a0h, a1l, a1h, a2l, a2h, a3l, a3h;
        unpack2(acc[0][o], a0l, a0h);
        unpack2(acc[1][o], a1l, a1h);
        unpack2(acc[2][o], a2l, a2h);
        unpack2(acc[3][o], a3l, a3h);
        int oc = h * 8 + 2 * o;
        float scl = ssc[oc], shl = ssh[oc];
        float mlo = fmaxf(fmaxf(fmaxf(a0l * scl + shl, 0.f),
                                fmaxf(a1l * scl + shl, 0.f)),
                          fmaxf(fmaxf(a2l * scl + shl, 0.f),
                                fmaxf(a3l * scl + shl, 0.f)));
        float sch = ssc[oc + 1], shh = ssh[oc + 1];
        float mhi = fmaxf(fmaxf(fmaxf(a0h * sch + shh, 0.f),
                                fmaxf(a1h * sch + shh, 0.f)),
                          fmaxf(fmaxf(a2h * sch + shh, 0.f),
                                fmaxf(a3h * sch + shh, 0.f)));
        r4[o] = pack_h2(mlo, mhi);
    }

    int gpy = ty * 16 + py, gpx = tx * 16 + px;
    *(int4*)(g_h1h + (((size_t)b * 32 + gpy) * 32 + gpx) * 16 + h * 8) =
        make_int4(r4[0], r4[1], r4[2], r4[3]);
}

// ---------------------------------------------------------------------------
// conv2: (b,32,32,16) half NHWC -> (b,16,16,32) half NHWC. (R11, proven)
// ---------------------------------------------------------------------------
__global__ __launch_bounds__(512) void conv2_kernel(
    const float* __restrict__ cb,
    const float* __restrict__ bg, const float* __restrict__ bb,
    const float* __restrict__ bm, const float* __restrict__ bv)
{
    __shared__ __align__(16) char usmem[36864];
    __shared__ float ssc[32], ssh[32];
    __half* sp2 = (__half*)usmem;
    __half* wb2 = (__half*)(usmem + 15552);
    float*  buf = (float*)usmem;

    int b = blockIdx.z, ty = blockIdx.y, tx = blockIdx.x;
    int tid = threadIdx.x;

    for (int i = tid; i < 608; i += 512)
        ((int4*)wb2)[i] = ((const int4*)g_wb2h)[i];
    if (tid < 32) {
        float inv = bg[tid] * rsqrtf(bv[tid] + 1e-5f);
        ssc[tid] = inv;
        ssh[tid] = (cb[tid] - bm[tid]) * inv + bb[tid];
    }
    int y0 = ty * 16 - 1, x0 = tx * 16 - 1;
    const __half* ib = g_h1h + (size_t)b * 1024 * 16;
    for (int i = tid; i < 324 * 2; i += 512) {
        int pix = i >> 1, j = i & 1;
        int yy = pix / 18, xx = pix % 18;
        int gy = y0 + yy, gx = x0 + xx;
        int4 v = make_int4(0, 0, 0, 0);
        if ((unsigned)gy < 32u && (unsigned)gx < 32u)
            v = *(const int4*)(ib + ((size_t)gy * 32 + gx) * 16 + j * 8);
        *(int4*)(sp2 + pix * 24 + j * 8) = v;
    }
    __syncthreads();

    int lane = tid & 31, warp = tid >> 5;
    int g = lane >> 2, tg = lane & 3;
    int mt = warp;

    int pxl = lane & 15, kha = lane >> 4;
    u32 aB = s2u(sp2) + (u32)(mt * 18 + pxl) * 48 + kha * 16;
    int ocl = (lane & 7) | ((lane >> 4) << 3);
    int khb = (lane >> 3) & 1;
    u32 bB0 = s2u(wb2) + (u32)ocl * 304 + khb * 16;
    u32 bB1 = bB0 + 16 * 304;

    float acc[4][4];
#pragma unroll
    for (int nt = 0; nt < 4; nt++)
#pragma unroll
        for (int r = 0; r < 4; r++) acc[nt][r] = 0.f;

#pragma unroll
    for (int tap = 0; tap < 9; tap++) {
        const int ky = tap / 3, kx = tap % 3;
        u32 a0, a1, a2, a3;
        ldsm_x4(a0, a1, a2, a3, aB + (u32)(ky * 18 + kx) * 48);
        u32 p00, p01, p10, p11, p20, p21, p30, p31;
        ldsm_x4(p00, p01, p10, p11, bB0 + tap * 32);
        ldsm_x4(p20, p21, p30, p31, bB1 + tap * 32);
        mma16(acc[0], a0, a1, a2, a3, p00, p01);
        mma16(acc[1], a0, a1, a2, a3, p10, p11);
        mma16(acc[2], a0, a1, a2, a3, p20, p21);
        mma16(acc[3], a0, a1, a2, a3, p30, p31);
    }

    __syncthreads();

    int m0 = mt * 16 + g;
#pragma unroll
    for (int nt = 0; nt < 4; nt++) {
        buf[m0 * 36 + nt * 8 + 2 * tg]           = acc[nt][0];
        buf[m0 * 36 + nt * 8 + 2 * tg + 1]       = acc[nt][1];
        buf[(m0 + 8) * 36 + nt * 8 + 2 * tg]     = acc[nt][2];
        buf[(m0 + 8) * 36 + nt * 8 + 2 * tg + 1] = acc[nt][3];
    }
    __syncthreads();

    {
        int pix = tid >> 3, ocg = tid & 7;
        int r = pix >> 3, Px = pix & 7;
        int ml = (2 * r) * 16 + 2 * Px;
        int oc0 = ocg * 4;
        float pv[4];
#pragma unroll
        for (int cc = 0; cc < 4; cc++) {
            int c = oc0 + cc;
            float sc = ssc[c], sh = ssh[c];
            float v0 = fmaxf(buf[ml * 36 + c] * sc + sh, 0.f);
            float v1 = fmaxf(buf[(ml + 1) * 36 + c] * sc + sh, 0.f);
            float v2 = fmaxf(buf[(ml + 16) * 36 + c] * sc + sh, 0.f);
            float v3 = fmaxf(buf[(ml + 17) * 36 + c] * sc + sh, 0.f);
            pv[cc] = fmaxf(fmaxf(v0, v1), fmaxf(v2, v3));
        }
        int gy = ty * 8 + r, gx = tx * 8 + Px;
        int2 ov = make_int2(pack_h2(pv[0], pv[1]), pack_h2(pv[2], pv[3]));
        *(int2*)(g_h2h + (((size_t)b * 16 + gy) * 16 + gx) * 32 + oc0) = ov;
    }
}

// ---------------------------------------------------------------------------
// conv3 + head fused, 2 blocks/SM. Warp tiling: 2 mtiles x 4 ntiles
// (8 m-groups x 2 n-groups) for balanced LDSM and doubled fragment ILP.
// ---------------------------------------------------------------------------
#define C3_SFE   69632
#define C3_BN    86016
#define C3_TOTAL 86528
#define H_SPART 0
#define H_SCOS  16384
#define H_SFT   16896
#define H_SCP   19200

__global__ __launch_bounds__(512, 2) void conv3_head_kernel(
    const float* __restrict__ cb,
    const float* __restrict__ bg, const float* __restrict__ bb,
    const float* __restrict__ bm, const float* __restrict__ bv,
    const float* __restrict__ pw, const float* __restrict__ pb,
    const float* __restrict__ cw, const float* __restrict__ cbias,
    float* __restrict__ out)
{
    extern __shared__ char smem_raw[];
    __half* sp3 = (__half*)(smem_raw + 0);
    __half* wb3 = (__half*)(smem_raw + 25920);
    float*  buf = (float*)(smem_raw + 0);
    float*  sfeats = (float*)(smem_raw + C3_SFE);
    float*  ssc = (float*)(smem_raw + C3_BN);
    float*  ssh = ssc + 64;

    int b = blockIdx.x, tid = threadIdx.x;

    for (int i = tid; i < 2368; i += 512)
        ((int4*)wb3)[i] = ((const int4*)g_wb3h)[i];
    if (tid < 64) {
        float inv = bg[tid] * rsqrtf(bv[tid] + 1e-5f);
        ssc[tid] = inv;
        ssh[tid] = (cb[tid] - bm[tid]) * inv + bb[tid];
    }
    const __half* ib = g_h2h + (size_t)b * 256 * 32;
    for (int i = tid; i < 324 * 4; i += 512) {
        int pix = i >> 2, j = i & 3;
        int yy = pix / 18, xx = pix % 18;
        int gy = yy - 1, gx = xx - 1;
        int4 v = make_int4(0, 0, 0, 0);
        if ((unsigned)gy < 16u && (unsigned)gx < 16u)
            v = *(const int4*)(ib + ((size_t)gy * 16 + gx) * 32 + j * 8);
        *(int4*)(sp3 + pix * 40 + j * 8) = v;
    }
    __syncthreads();

    int lane = tid & 31, warp = tid >> 5;
    int g = lane >> 2, tg = lane & 3;
    int mg = warp & 7, ng = warp >> 3;          // 2 mtiles, 4 ntiles per warp

    int pxl = lane & 15, kha = lane >> 4;
    u32 aB0 = s2u(sp3) + (u32)((2 * mg) * 18 + pxl) * 80 + kha * 16;
    u32 aB1 = aB0 + 18 * 80;
    int ocl = (lane & 7) | ((lane >> 4) << 3);
    int khb = (lane >> 3) & 1;
    u32 bB0 = s2u(wb3) + (u32)ocl * 592 + khb * 16 + (u32)(2 * ng) * 16 * 592;
    u32 bB1 = bB0 + 16 * 592;

    float acc[2][4][4];
#pragma unroll
    for (int mi = 0; mi < 2; mi++)
#pragma unroll
        for (int nt = 0; nt < 4; nt++)
#pragma unroll
            for (int r = 0; r < 4; r++) acc[mi][nt][r] = 0.f;

#pragma unroll
    for (int kt = 0; kt < 18; kt++) {
        const int tap = kt >> 1, h = kt & 1;
        const int ky = tap / 3, kx = tap % 3;
        const u32 aoff = (u32)(ky * 18 + kx) * 80 + h * 32;
        u32 x0, x1, x2, x3, y0, y1, y2, y3;
        ldsm_x4(x0, x1, x2, x3, aB0 + aoff);
        ldsm_x4(y0, y1, y2, y3, aB1 + aoff);
        u32 p0, p1, p2, p3, q0, q1, q2, q3;
        ldsm_x4(p0, p1, p2, p3, bB0 + kt * 32);
        ldsm_x4(q0, q1, q2, q3, bB1 + kt * 32);
        mma16(acc[0][0], x0, x1, x2, x3, p0, p1);
        mma16(acc[0][1], x0, x1, x2, x3, p2, p3);
        mma16(acc[0][2], x0, x1, x2, x3, q0, q1);
        mma16(acc[0][3], x0, x1, x2, x3, q2, q3);
        mma16(acc[1][0], y0, y1, y2, y3, p0, p1);
        mma16(acc[1][1], y0, y1, y2, y3, p2, p3);
        mma16(acc[1][2], y0, y1, y2, y3, q0, q1);
        mma16(acc[1][3], y0, y1, y2, y3, q2, q3);
    }

    __syncthreads();

#pragma unroll
    for (int mi = 0; mi < 2; mi++) {
        int m0 = (2 * mg + mi) * 16 + g;
#pragma unroll
        for (int nt = 0; nt < 4; nt++) {
            int col = (ng * 4 + nt) * 8 + 2 * tg;
            buf[m0 * 68 + col]           = acc[mi][nt][0];
            buf[m0 * 68 + col + 1]       = acc[mi][nt][1];
            buf[(m0 + 8) * 68 + col]     = acc[mi][nt][2];
            buf[(m0 + 8) * 68 + col + 1] = acc[mi][nt][3];
        }
    }
    __syncthreads();

    {
        int pix = tid >> 3, ocg = tid & 7;
        int r = pix >> 3, Px = pix & 7;
        int ml = (2 * r) * 16 + 2 * Px;
        int oc0 = ocg * 8;
#pragma unroll
        for (int cc = 0; cc < 8; cc++) {
            int c = oc0 + cc;
            float sc = ssc[c], sh = ssh[c];
            float v0 = fmaxf(buf[ml * 68 + c] * sc + sh, 0.f);
            float v1 = fmaxf(buf[(ml + 1) * 68 + c] * sc + sh, 0.f);
            float v2 = fmaxf(buf[(ml + 16) * 68 + c] * sc + sh, 0.f);
            float v3 = fmaxf(buf[(ml + 17) * 68 + c] * sc + sh, 0.f);
            sfeats[c * 64 + r * 8 + Px] = fmaxf(fmaxf(v0, v1), fmaxf(v2, v3));
        }
    }
    __syncthreads();

    // ---- head ----
    float* spart = (float*)(smem_raw + H_SPART);
    float* scos  = (float*)(smem_raw + H_SCOS);
    float* sfeat = (float*)(smem_raw + H_SFT);
    float* scp   = (float*)(smem_raw + H_SCP);

    {
        int k = tid >> 5, cs = tid & 31;
        float part[8];
#pragma unroll
        for (int d = 0; d < 8; d++) part[d] = 0.f;
        const float* fr = sfeats + k * 256 + cs * 8;
        const float* wr = pw + k * 2048 + cs * 64;
#pragma unroll
        for (int c = 0; c < 8; c++) {
            float fv = fr[c];
            float4 w0 = ((const float4*)(wr + c * 8))[0];
            float4 w1 = ((const float4*)(wr + c * 8))[1];
            part[0] += fv * w0.x; part[1] += fv * w0.y;
            part[2] += fv * w0.z; part[3] += fv * w0.w;
            part[4] += fv * w1.x; part[5] += fv * w1.y;
            part[6] += fv * w1.z; part[7] += fv * w1.w;
        }
        __syncthreads();
#pragma unroll
        for (int d = 0; d < 8; d++) spart[tid * 8 + d] = part[d];
    }
    __syncthreads();

    if (tid < 128) {
        int k = tid >> 3, d = tid & 7;
        float z = pb[k * 8 + d];
#pragma unroll
        for (int cs = 0; cs < 32; cs++) z += spart[(k * 32 + cs) * 8 + d];
        scos[tid] = cosf(0.5f * tanhf(z));
    }
    __syncthreads();

    if (tid < 16) {
        const float* c8 = scos + tid * 8;
        float* fo = sfeat + tid * 36;
        float p = 1.f;
#pragma unroll
        for (int q = 0; q < 8; q++) { p *= c8[q]; fo[q] = p; }
        int idx = 8;
#pragma unroll
        for (int i = 0; i < 8; i++) {
#pragma unroll
            for (int j = i + 1; j < 8; j++) {
                float p2 = 1.f;
                for (int m = i + 1; m <= j; m++) p2 *= c8[m];
                fo[idx++] = p2;
            }
        }
    }
    __syncthreads();

    if (tid < 80) {
        int cls = tid >> 3, ch = tid & 7;
        const float* wrow = cw + cls * 576 + ch * 72;
        const float* fr2 = sfeat + ch * 72;
        float s = 0.f;
#pragma unroll 8
        for (int j = 0; j < 72; j++) s += fr2[j] * wrow[j];
        scp[cls * 8 + ch] = s;
    }
    __syncthreads();

    if (tid < 10) {
        float o = cbias[tid];
#pragma unroll
        for (int ch = 0; ch < 8; ch++) o += scp[tid * 8 + ch];
        out[b * 10 + tid] = o;
    }
}

// ---------------------------------------------------------------------------
extern "C" void kernel_launch(void* const* d_in, const int* in_sizes, int n_in,
                              void* d_out, int out_size)
{
    const float* x    = (const float*)d_in[0];
    const float* c1w  = (const float*)d_in[1];
    const float* c1b  = (const float*)d_in[2];
    const float* g1   = (const float*)d_in[3];
    const float* b1   = (const float*)d_in[4];
    const float* m1   = (const float*)d_in[5];
    const float* v1   = (const float*)d_in[6];
    const float* c2w  = (const float*)d_in[7];
    const float* c2b  = (const float*)d_in[8];
    const float* g2   = (const float*)d_in[9];
    const float* b2   = (const float*)d_in[10];
    const float* m2   = (const float*)d_in[11];
    const float* v2   = (const float*)d_in[12];
    const float* c3w  = (const float*)d_in[13];
    const float* c3b  = (const float*)d_in[14];
    const float* g3   = (const float*)d_in[15];
    const float* b3   = (const float*)d_in[16];
    const float* m3   = (const float*)d_in[17];
    const float* v3   = (const float*)d_in[18];
    const float* pw   = (const float*)d_in[19];
    const float* pb   = (const float*)d_in[20];
    const float* cw   = (const float*)d_in[21];
    const float* cbias= (const float*)d_in[22];
    float* out = (float*)d_out;

    cudaFuncSetAttribute(conv3_head_kernel,
                         cudaFuncAttributeMaxDynamicSharedMemorySize, C3_TOTAL);

    prep_kernel<<<74, 256>>>(c2w, c3w);
    conv1_kernel<<<dim3(2, 2, 512), 512>>>(x, c1w, c1b, g1, b1, m1, v1);
    conv2_kernel<<<dim3(2, 2, 512), 512>>>(c2b, g2, b2, m2, v2);
    conv3_head_kernel<<<512, 512, C3_TOTAL>>>(c3b, g3, b3, m3, v3,
                                              pw, pb, cw, cbias, out);
}

// round 16
// speedup vs baseline: 1.5453x; 1.0681x over previous
#include <cuda_runtime.h>
#include <cuda_fp16.h>
#include <cstdint>

// ---------------------------------------------------------------------------
// HybridModel, Round 15:
//   prep: one-time fp16 weight repack for conv2/conv3
//   conv1: FFMA2 direct conv, 512 thr (proven)
//   conv2: fp16 mma + ldmatrix; buf stride 37 (reduced bank conflicts)
//   conv3_head: 2x4 warp tiling; buf stride 69 (conflict-free epilogue);
//               classifier widened to 320 threads
// ---------------------------------------------------------------------------

typedef uint32_t u32;
typedef unsigned long long ull;

__device__ __forceinline__ void ffma2(ull& d, ull a, ull b) {
    asm("fma.rn.f32x2 %0, %1, %2, %0;" : "+l"(d) : "l"(a), "l"(b));
}
__device__ __forceinline__ ull dup2(float v) {
    ull r;
    asm("mov.b64 %0, {%1, %1};" : "=l"(r) : "f"(v));
    return r;
}
__device__ __forceinline__ void unpack2(ull v, float& lo, float& hi) {
    asm("mov.b64 {%0, %1}, %2;" : "=f"(lo), "=f"(hi) : "l"(v));
}

__device__ __forceinline__ void mma16(float* d, u32 a0, u32 a1, u32 a2, u32 a3,
                                      u32 b0, u32 b1) {
    asm("mma.sync.aligned.m16n8k16.row.col.f32.f16.f16.f32 "
        "{%0,%1,%2,%3},{%4,%5,%6,%7},{%8,%9},{%0,%1,%2,%3};"
        : "+f"(d[0]), "+f"(d[1]), "+f"(d[2]), "+f"(d[3])
        : "r"(a0), "r"(a1), "r"(a2), "r"(a3), "r"(b0), "r"(b1));
}

__device__ __forceinline__ void ldsm_x4(u32& r0, u32& r1, u32& r2, u32& r3,
                                        u32 addr) {
    asm volatile("ldmatrix.sync.aligned.m8n8.x4.shared.b16 {%0,%1,%2,%3}, [%4];"
        : "=r"(r0), "=r"(r1), "=r"(r2), "=r"(r3) : "r"(addr));
}

__device__ __forceinline__ u32 s2u(const void* p) {
    return (u32)__cvta_generic_to_shared(p);
}

__device__ __forceinline__ u32 pack_h2(float lo, float hi) {
    __half2 h = __floats2half2_rn(lo, hi);
    return *(u32*)&h;
}

// fp16 NHWC intermediates
__device__ __half g_h1h[512 * 32 * 32 * 16];   // 16.8 MB, [b][y][x][c16]
__device__ __half g_h2h[512 * 16 * 16 * 32];   //  8.4 MB, [b][y][x][c32]
// prepacked fp16 weights (exact smem layouts, tails zeroed)
__device__ __align__(16) __half g_wb2h[32 * 152];
__device__ __align__(16) __half g_wb3h[64 * 296];

// ---------------------------------------------------------------------------
// prep: repack conv2/conv3 weights to fp16 padded layouts (one launch).
// ---------------------------------------------------------------------------
__global__ __launch_bounds__(256) void prep_kernel(
    const float* __restrict__ w2, const float* __restrict__ w3)
{
    int i = blockIdx.x * 256 + threadIdx.x;
    if (i < 32 * 152) {
        int oc = i / 152, k = i % 152;
        float v = 0.f;
        if (k < 144) { int tap = k >> 4, ic = k & 15; v = w2[oc * 144 + ic * 9 + tap]; }
        g_wb2h[i] = __float2half_rn(v);
    }
    if (i < 64 * 296) {
        int oc = i / 296, k = i % 296;
        float v = 0.f;
        if (k < 288) { int tap = k >> 5, ic = k & 31; v = w3[(oc * 32 + ic) * 9 + tap]; }
        g_wb3h[i] = __float2half_rn(v);
    }
}

// ---------------------------------------------------------------------------
// conv1: (b,3,64,64) f32 -> bn/relu/pool -> (b,32,32,16) half NHWC (proven)
// ---------------------------------------------------------------------------
__global__ __launch_bounds__(512, 2) void conv1_kernel(
    const float* __restrict__ x, const float* __restrict__ w,
    const float* __restrict__ cb, const float* __restrict__ bg,
    const float* __restrict__ bb, const float* __restrict__ bm,
    const float* __restrict__ bv)
{
    __shared__ __align__(16) float sp[3][34][34];
    __shared__ __align__(16) float swt[3][9][16];
    __shared__ float ssc[16], ssh[16];

    int b = blockIdx.z, ty = blockIdx.y, tx = blockIdx.x;
    int tid = threadIdx.x;

    for (int i = tid; i < 16 * 27; i += 512) {
        int oc = i / 27, r = i % 27, ic = r / 9, k = r % 9;
        swt[ic][k][oc] = w[i];
    }
    if (tid < 16) {
        float inv = bg[tid] * rsqrtf(bv[tid] + 1e-5f);
        ssc[tid] = inv;
        ssh[tid] = (cb[tid] - bm[tid]) * inv + bb[tid];
    }
    int y0 = ty * 32 - 1, x0 = tx * 32 - 1;
    const float* xb = x + b * 3 * 64 * 64;
    for (int i = tid; i < 3 * 34 * 34; i += 512) {
        int ic = i / 1156, r = i % 1156, yy = r / 34, xx = r % 34;
        int gy = y0 + yy, gx = x0 + xx;
        float val = 0.f;
        if ((unsigned)gy < 64u && (unsigned)gx < 64u)
            val = xb[(ic * 64 + gy) * 64 + gx];
        sp[ic][yy][xx] = val;
    }
    __syncthreads();

    int pix = tid & 255, h = tid >> 8;
    int py = pix >> 4, px = pix & 15;
    int by = 2 * py, bx = 2 * px;

    ull acc[4][4];
#pragma unroll
    for (int p = 0; p < 4; p++)
#pragma unroll
        for (int o = 0; o < 4; o++) acc[p][o] = 0ull;

#pragma unroll 1
    for (int ic = 0; ic < 3; ic++) {
#pragma unroll
        for (int k = 0; k < 9; k++) {
            const int ky = k / 3, kx = k % 3;
            ull d00 = dup2(sp[ic][by + ky][bx + kx]);
            ull d01 = dup2(sp[ic][by + ky][bx + kx + 1]);
            ull d10 = dup2(sp[ic][by + ky + 1][bx + kx]);
            ull d11 = dup2(sp[ic][by + ky + 1][bx + kx + 1]);
            const ull* wp = (const ull*)swt[ic][k] + h * 4;
#pragma unroll
            for (int o = 0; o < 4; o++) {
                ull wv = wp[o];
                ffma2(acc[0][o], d00, wv);
                ffma2(acc[1][o], d01, wv);
                ffma2(acc[2][o], d10, wv);
                ffma2(acc[3][o], d11, wv);
            }
        }
    }

    u32 r4[4];
#pragma unroll
    for (int o = 0; o < 4; o++) {
        float a0l, a0h, a1l, a1h, a2l, a2h, a3l, a3h;
        unpack2(acc[0][o], a0l, a0h);
        unpack2(acc[1][o], a1l, a1h);
        unpack2(acc[2][o], a2l, a2h);
        unpack2(acc[3][o], a3l, a3h);
        int oc = h * 8 + 2 * o;
        float scl = ssc[oc], shl = ssh[oc];
        float mlo = fmaxf(fmaxf(fmaxf(a0l * scl + shl, 0.f),
                                fmaxf(a1l * scl + shl, 0.f)),
                          fmaxf(fmaxf(a2l * scl + shl, 0.f),
                                fmaxf(a3l * scl + shl, 0.f)));
        float sch = ssc[oc + 1], shh = ssh[oc + 1];
        float mhi = fmaxf(fmaxf(fmaxf(a0h * sch + shh, 0.f),
                                fmaxf(a1h * sch + shh, 0.f)),
                          fmaxf(fmaxf(a2h * sch + shh, 0.f),
                                fmaxf(a3h * sch + shh, 0.f)));
        r4[o] = pack_h2(mlo, mhi);
    }

    int gpy = ty * 16 + py, gpx = tx * 16 + px;
    *(int4*)(g_h1h + (((size_t)b * 32 + gpy) * 32 + gpx) * 16 + h * 8) =
        make_int4(r4[0], r4[1], r4[2], r4[3]);
}

// ---------------------------------------------------------------------------
// conv2: (b,32,32,16) half NHWC -> (b,16,16,32) half NHWC. buf stride 37.
// ---------------------------------------------------------------------------
__global__ __launch_bounds__(512) void conv2_kernel(
    const float* __restrict__ cb,
    const float* __restrict__ bg, const float* __restrict__ bb,
    const float* __restrict__ bm, const float* __restrict__ bv)
{
    __shared__ __align__(16) char usmem[38912];   // buf 256*37*4 = 37888
    __shared__ float ssc[32], ssh[32];
    __half* sp2 = (__half*)usmem;
    __half* wb2 = (__half*)(usmem + 15552);
    float*  buf = (float*)usmem;

    int b = blockIdx.z, ty = blockIdx.y, tx = blockIdx.x;
    int tid = threadIdx.x;

    for (int i = tid; i < 608; i += 512)
        ((int4*)wb2)[i] = ((const int4*)g_wb2h)[i];
    if (tid < 32) {
        float inv = bg[tid] * rsqrtf(bv[tid] + 1e-5f);
        ssc[tid] = inv;
        ssh[tid] = (cb[tid] - bm[tid]) * inv + bb[tid];
    }
    int y0 = ty * 16 - 1, x0 = tx * 16 - 1;
    const __half* ib = g_h1h + (size_t)b * 1024 * 16;
    for (int i = tid; i < 324 * 2; i += 512) {
        int pix = i >> 1, j = i & 1;
        int yy = pix / 18, xx = pix % 18;
        int gy = y0 + yy, gx = x0 + xx;
        int4 v = make_int4(0, 0, 0, 0);
        if ((unsigned)gy < 32u && (unsigned)gx < 32u)
            v = *(const int4*)(ib + ((size_t)gy * 32 + gx) * 16 + j * 8);
        *(int4*)(sp2 + pix * 24 + j * 8) = v;
    }
    __syncthreads();

    int lane = tid & 31, warp = tid >> 5;
    int g = lane >> 2, tg = lane & 3;
    int mt = warp;

    int pxl = lane & 15, kha = lane >> 4;
    u32 aB = s2u(sp2) + (u32)(mt * 18 + pxl) * 48 + kha * 16;
    int ocl = (lane & 7) | ((lane >> 4) << 3);
    int khb = (lane >> 3) & 1;
    u32 bB0 = s2u(wb2) + (u32)ocl * 304 + khb * 16;
    u32 bB1 = bB0 + 16 * 304;

    float acc[4][4];
#pragma unroll
    for (int nt = 0; nt < 4; nt++)
#pragma unroll
        for (int r = 0; r < 4; r++) acc[nt][r] = 0.f;

#pragma unroll
    for (int tap = 0; tap < 9; tap++) {
        const int ky = tap / 3, kx = tap % 3;
        u32 a0, a1, a2, a3;
        ldsm_x4(a0, a1, a2, a3, aB + (u32)(ky * 18 + kx) * 48);
        u32 p00, p01, p10, p11, p20, p21, p30, p31;
        ldsm_x4(p00, p01, p10, p11, bB0 + tap * 32);
        ldsm_x4(p20, p21, p30, p31, bB1 + tap * 32);
        mma16(acc[0], a0, a1, a2, a3, p00, p01);
        mma16(acc[1], a0, a1, a2, a3, p10, p11);
        mma16(acc[2], a0, a1, a2, a3, p20, p21);
        mma16(acc[3], a0, a1, a2, a3, p30, p31);
    }

    __syncthreads();

    int m0 = mt * 16 + g;
#pragma unroll
    for (int nt = 0; nt < 4; nt++) {
        buf[m0 * 37 + nt * 8 + 2 * tg]           = acc[nt][0];
        buf[m0 * 37 + nt * 8 + 2 * tg + 1]       = acc[nt][1];
        buf[(m0 + 8) * 37 + nt * 8 + 2 * tg]     = acc[nt][2];
        buf[(m0 + 8) * 37 + nt * 8 + 2 * tg + 1] = acc[nt][3];
    }
    __syncthreads();

    {
        int pix = tid >> 3, ocg = tid & 7;
        int r = pix >> 3, Px = pix & 7;
        int ml = (2 * r) * 16 + 2 * Px;
        int oc0 = ocg * 4;
        float pv[4];
#pragma unroll
        for (int cc = 0; cc < 4; cc++) {
            int c = oc0 + cc;
            float sc = ssc[c], sh = ssh[c];
            float v0 = fmaxf(buf[ml * 37 + c] * sc + sh, 0.f);
            float v1 = fmaxf(buf[(ml + 1) * 37 + c] * sc + sh, 0.f);
            float v2 = fmaxf(buf[(ml + 16) * 37 + c] * sc + sh, 0.f);
            float v3 = fmaxf(buf[(ml + 17) * 37 + c] * sc + sh, 0.f);
            pv[cc] = fmaxf(fmaxf(v0, v1), fmaxf(v2, v3));
        }
        int gy = ty * 8 + r, gx = tx * 8 + Px;
        int2 ov = make_int2(pack_h2(pv[0], pv[1]), pack_h2(pv[2], pv[3]));
        *(int2*)(g_h2h + (((size_t)b * 16 + gy) * 16 + gx) * 32 + oc0) = ov;
    }
}

// ---------------------------------------------------------------------------
// conv3 + head fused, 2 blocks/SM, 2x4 warp tiling, buf stride 69.
// ---------------------------------------------------------------------------
#define C3_SFE   70656                     // buf 256*69*4 = 70656
#define C3_BN    87040
#define C3_TOTAL 87552
#define H_SPART 0
#define H_SCOS  16384
#define H_SFT   16896
#define H_SCP   19200                      // 320 floats -> 20480

__global__ __launch_bounds__(512, 2) void conv3_head_kernel(
    const float* __restrict__ cb,
    const float* __restrict__ bg, const float* __restrict__ bb,
    const float* __restrict__ bm, const float* __restrict__ bv,
    const float* __restrict__ pw, const float* __restrict__ pb,
    const float* __restrict__ cw, const float* __restrict__ cbias,
    float* __restrict__ out)
{
    extern __shared__ char smem_raw[];
    __half* sp3 = (__half*)(smem_raw + 0);
    __half* wb3 = (__half*)(smem_raw + 25920);
    float*  buf = (float*)(smem_raw + 0);
    float*  sfeats = (float*)(smem_raw + C3_SFE);
    float*  ssc = (float*)(smem_raw + C3_BN);
    float*  ssh = ssc + 64;

    int b = blockIdx.x, tid = threadIdx.x;

    for (int i = tid; i < 2368; i += 512)
        ((int4*)wb3)[i] = ((const int4*)g_wb3h)[i];
    if (tid < 64) {
        float inv = bg[tid] * rsqrtf(bv[tid] + 1e-5f);
        ssc[tid] = inv;
        ssh[tid] = (cb[tid] - bm[tid]) * inv + bb[tid];
    }
    const __half* ib = g_h2h + (size_t)b * 256 * 32;
    for (int i = tid; i < 324 * 4; i += 512) {
        int pix = i >> 2, j = i & 3;
        int yy = pix / 18, xx = pix % 18;
        int gy = yy - 1, gx = xx - 1;
        int4 v = make_int4(0, 0, 0, 0);
        if ((unsigned)gy < 16u && (unsigned)gx < 16u)
            v = *(const int4*)(ib + ((size_t)gy * 16 + gx) * 32 + j * 8);
        *(int4*)(sp3 + pix * 40 + j * 8) = v;
    }
    __syncthreads();

    int lane = tid & 31, warp = tid >> 5;
    int g = lane >> 2, tg = lane & 3;
    int mg = warp & 7, ng = warp >> 3;          // 2 mtiles x 4 ntiles per warp

    int pxl = lane & 15, kha = lane >> 4;
    u32 aB0 = s2u(sp3) + (u32)((2 * mg) * 18 + pxl) * 80 + kha * 16;
    u32 aB1 = aB0 + 18 * 80;
    int ocl = (lane & 7) | ((lane >> 4) << 3);
    int khb = (lane >> 3) & 1;
    u32 bB0 = s2u(wb3) + (u32)ocl * 592 + khb * 16 + (u32)(2 * ng) * 16 * 592;
    u32 bB1 = bB0 + 16 * 592;

    float acc[2][4][4];
#pragma unroll
    for (int mi = 0; mi < 2; mi++)
#pragma unroll
        for (int nt = 0; nt < 4; nt++)
#pragma unroll
            for (int r = 0; r < 4; r++) acc[mi][nt][r] = 0.f;

#pragma unroll
    for (int kt = 0; kt < 18; kt++) {
        const int tap = kt >> 1, h = kt & 1;
        const int ky = tap / 3, kx = tap % 3;
        const u32 aoff = (u32)(ky * 18 + kx) * 80 + h * 32;
        u32 x0, x1, x2, x3, y0, y1, y2, y3;
        ldsm_x4(x0, x1, x2, x3, aB0 + aoff);
        ldsm_x4(y0, y1, y2, y3, aB1 + aoff);
        u32 p0, p1, p2, p3, q0, q1, q2, q3;
        ldsm_x4(p0, p1, p2, p3, bB0 + kt * 32);
        ldsm_x4(q0, q1, q2, q3, bB1 + kt * 32);
        mma16(acc[0][0], x0, x1, x2, x3, p0, p1);
        mma16(acc[0][1], x0, x1, x2, x3, p2, p3);
        mma16(acc[0][2], x0, x1, x2, x3, q0, q1);
        mma16(acc[0][3], x0, x1, x2, x3, q2, q3);
        mma16(acc[1][0], y0, y1, y2, y3, p0, p1);
        mma16(acc[1][1], y0, y1, y2, y3, p2, p3);
        mma16(acc[1][2], y0, y1, y2, y3, q0, q1);
        mma16(acc[1][3], y0, y1, y2, y3, q2, q3);
    }

    __syncthreads();

#pragma unroll
    for (int mi = 0; mi < 2; mi++) {
        int m0 = (2 * mg + mi) * 16 + g;
#pragma unroll
        for (int nt = 0; nt < 4; nt++) {
            int col = (ng * 4 + nt) * 8 + 2 * tg;
            buf[m0 * 69 + col]           = acc[mi][nt][0];
            buf[m0 * 69 + col + 1]       = acc[mi][nt][1];
            buf[(m0 + 8) * 69 + col]     = acc[mi][nt][2];
            buf[(m0 + 8) * 69 + col + 1] = acc[mi][nt][3];
        }
    }
    __syncthreads();

    {
        int pix = tid >> 3, ocg = tid & 7;
        int r = pix >> 3, Px = pix & 7;
        int ml = (2 * r) * 16 + 2 * Px;
        int oc0 = ocg * 8;
#pragma unroll
        for (int cc = 0; cc < 8; cc++) {
            int c = oc0 + cc;
            float sc = ssc[c], sh = ssh[c];
            float v0 = fmaxf(buf[ml * 69 + c] * sc + sh, 0.f);
            float v1 = fmaxf(buf[(ml + 1) * 69 + c] * sc + sh, 0.f);
            float v2 = fmaxf(buf[(ml + 16) * 69 + c] * sc + sh, 0.f);
            float v3 = fmaxf(buf[(ml + 17) * 69 + c] * sc + sh, 0.f);
            sfeats[c * 64 + r * 8 + Px] = fmaxf(fmaxf(v0, v1), fmaxf(v2, v3));
        }
    }
    __syncthreads();

    // ---- head ----
    float* spart = (float*)(smem_raw + H_SPART);
    float* scos  = (float*)(smem_raw + H_SCOS);
    float* sfeat = (float*)(smem_raw + H_SFT);
    float* scp   = (float*)(smem_raw + H_SCP);

    {
        int k = tid >> 5, cs = tid & 31;
        float part[8];
#pragma unroll
        for (int d = 0; d < 8; d++) part[d] = 0.f;
        const float* fr = sfeats + k * 256 + cs * 8;
        const float* wr = pw + k * 2048 + cs * 64;
#pragma unroll
        for (int c = 0; c < 8; c++) {
            float fv = fr[c];
            float4 w0 = ((const float4*)(wr + c * 8))[0];
            float4 w1 = ((const float4*)(wr + c * 8))[1];
            part[0] += fv * w0.x; part[1] += fv * w0.y;
            part[2] += fv * w0.z; part[3] += fv * w0.w;
            part[4] += fv * w1.x; part[5] += fv * w1.y;
            part[6] += fv * w1.z; part[7] += fv * w1.w;
        }
        __syncthreads();
#pragma unroll
        for (int d = 0; d < 8; d++) spart[tid * 8 + d] = part[d];
    }
    __syncthreads();

    if (tid < 128) {
        int k = tid >> 3, d = tid & 7;
        float z = pb[k * 8 + d];
#pragma unroll
        for (int cs = 0; cs < 32; cs++) z += spart[(k * 32 + cs) * 8 + d];
        scos[tid] = cosf(0.5f * tanhf(z));
    }
    __syncthreads();

    if (tid < 16) {
        const float* c8 = scos + tid * 8;
        float* fo = sfeat + tid * 36;
        float p = 1.f;
#pragma unroll
        for (int q = 0; q < 8; q++) { p *= c8[q]; fo[q] = p; }
        int idx = 8;
#pragma unroll
        for (int i = 0; i < 8; i++) {
#pragma unroll
            for (int j = i + 1; j < 8; j++) {
                float p2 = 1.f;
                for (int m = i + 1; m <= j; m++) p2 *= c8[m];
                fo[idx++] = p2;
            }
        }
    }
    __syncthreads();

    // classifier stage 1: 320 threads x 18 features
    if (tid < 320) {
        int cls = tid >> 5, ch = tid & 31;
        const float* wrow = cw + cls * 576 + ch * 18;
        const float* fr2 = sfeat + ch * 18;
        float s = 0.f;
#pragma unroll
        for (int j = 0; j < 18; j++) s += fr2[j] * wrow[j];
        scp[cls * 32 + ch] = s;
    }
    __syncthreads();

    if (tid < 10) {
        float o = cbias[tid];
#pragma unroll
        for (int ch = 0; ch < 32; ch++) o += scp[tid * 32 + ch];
        out[b * 10 + tid] = o;
    }
}

// ---------------------------------------------------------------------------
extern "C" void kernel_launch(void* const* d_in, const int* in_sizes, int n_in,
                              void* d_out, int out_size)
{
    const float* x    = (const float*)d_in[0];
    const float* c1w  = (const float*)d_in[1];
    const float* c1b  = (const float*)d_in[2];
    const float* g1   = (const float*)d_in[3];
    const float* b1   = (const float*)d_in[4];
    const float* m1   = (const float*)d_in[5];
    const float* v1   = (const float*)d_in[6];
    const float* c2w  = (const float*)d_in[7];
    const float* c2b  = (const float*)d_in[8];
    const float* g2   = (const float*)d_in[9];
    const float* b2   = (const float*)d_in[10];
    const float* m2   = (const float*)d_in[11];
    const float* v2   = (const float*)d_in[12];
    const float* c3w  = (const float*)d_in[13];
    const float* c3b  = (const float*)d_in[14];
    const float* g3   = (const float*)d_in[15];
    const float* b3   = (const float*)d_in[16];
    const float* m3   = (const float*)d_in[17];
    const float* v3   = (const float*)d_in[18];
    const float* pw   = (const float*)d_in[19];
    const float* pb   = (const float*)d_in[20];
    const float* cw   = (const float*)d_in[21];
    const float* cbias= (const float*)d_in[22];
    float* out = (float*)d_out;

    cudaFuncSetAttribute(conv3_head_kernel,
                         cudaFuncAttributeMaxDynamicSharedMemorySize, C3_TOTAL);

    prep_kernel<<<74, 256>>>(c2w, c3w);
    conv1_kernel<<<dim3(2, 2, 512), 512>>>(x, c1w, c1b, g1, b1, m1, v1);
    conv2_kernel<<<dim3(2, 2, 512), 512>>>(c2b, g2, b2, m2, v2);
    conv3_head_kernel<<<512, 512, C3_TOTAL>>>(c3b, g3, b3, m3, v3,
                                              pw, pb, cw, cbias, out);
}